// round 10
// baseline (speedup 1.0000x reference)
#include <cuda_runtime.h>
#include <cuda_bf16.h>
#include <cstdint>
#include <math.h>

#define HH 2048
#define SS 4096
#define BB 4
#define RR 64
#define F7 (7*HH)

// ---------------- scratch (device globals; no allocation) ----------------
__device__ float d_rowsq[BB*SS];
__device__ float d_feats[BB*F7];
__device__ float d_a1[BB*1024];
__device__ float d_h1[BB*1024];
__device__ float d_a2[BB*512];
__device__ float d_h2[BB*512];
__device__ float d_a3[BB*256];
__device__ __nv_bfloat16 d_Ut[BB*RR*HH];   // [b][r][h]  (U transposed)
__device__ __nv_bfloat16 d_Vt[BB*HH*RR];   // [b][h][r]  (V transposed)

// ---------------- init (zero the atomic accumulators) ----------------
__global__ void k_init() {
    int i = blockIdx.x*256 + threadIdx.x;
    if (i < BB*SS)   d_rowsq[i] = 0.f;
    if (i < BB*1024) d_a1[i] = 0.f;
    if (i < BB*512)  d_a2[i] = 0.f;
    if (i < BB*256)  d_a3[i] = 0.f;
}

// ------- column stats + fused row sumsq (one pass over X, float4) -------
__global__ void __launch_bounds__(512) k_colstats(const float* __restrict__ X) {
    int b  = blockIdx.y;
    int c0 = blockIdx.x * 128;                 // 128 cols per block (32 lanes x 4)
    int t  = threadIdx.x, w = t >> 5, lane = t & 31;
    const float4* base = (const float4*)(X + (size_t)b*SS*HH + c0);
    float s1[4] = {0,0,0,0}, s2[4] = {0,0,0,0}, s3[4] = {0,0,0,0}, s4[4] = {0,0,0,0};
    float mx[4] = {-INFINITY,-INFINITY,-INFINITY,-INFINITY};
    float mn[4] = { INFINITY, INFINITY, INFINITY, INFINITY};
    for (int r = w; r < SS; r += 16) {
        float4 v = base[(size_t)r*(HH/4) + lane];
        float xs[4] = {v.x, v.y, v.z, v.w};
        float rs = 0.f;
        #pragma unroll
        for (int k = 0; k < 4; k++) {
            float x = xs[k], x2 = x*x;
            s1[k] += x; s2[k] += x2; s3[k] += x2*x; s4[k] += x2*x2;
            mx[k] = fmaxf(mx[k], x); mn[k] = fminf(mn[k], x);
            rs += x2;
        }
        #pragma unroll
        for (int o = 16; o; o >>= 1) rs += __shfl_xor_sync(0xffffffffu, rs, o);
        if (lane == 0) atomicAdd(&d_rowsq[b*SS + r], rs);
    }
    __shared__ float sm[6][16][32][4];         // 48 KB
    #pragma unroll
    for (int k = 0; k < 4; k++) {
        sm[0][w][lane][k] = s1[k]; sm[1][w][lane][k] = s2[k];
        sm[2][w][lane][k] = s3[k]; sm[3][w][lane][k] = s4[k];
        sm[4][w][lane][k] = mx[k]; sm[5][w][lane][k] = mn[k];
    }
    __syncthreads();
    if (t < 32) {
        float S1[4], S2[4], S3[4], S4[4], MX[4], MN[4];
        #pragma unroll
        for (int k = 0; k < 4; k++) {
            S1[k]=0.f; S2[k]=0.f; S3[k]=0.f; S4[k]=0.f;
            MX[k]=-INFINITY; MN[k]=INFINITY;
        }
        for (int g = 0; g < 16; g++) {
            #pragma unroll
            for (int k = 0; k < 4; k++) {
                S1[k] += sm[0][g][t][k]; S2[k] += sm[1][g][t][k];
                S3[k] += sm[2][g][t][k]; S4[k] += sm[3][g][t][k];
                MX[k] = fmaxf(MX[k], sm[4][g][t][k]);
                MN[k] = fminf(MN[k], sm[5][g][t][k]);
            }
        }
        const float inv = 1.f / (float)SS;
        float* f = d_feats + b*F7;
        #pragma unroll
        for (int k = 0; k < 4; k++) {
            float mu = S1[k]*inv, E2 = S2[k]*inv, E3 = S3[k]*inv, E4 = S4[k]*inv;
            float varu = fmaxf((S2[k] - (float)SS*mu*mu) / (float)(SS-1), 0.f);
            float sd = sqrtf(varu);
            float m3 = E3 - 3.f*mu*E2 + 2.f*mu*mu*mu;
            float m4 = E4 - 4.f*mu*E3 + 6.f*mu*mu*E2 - 3.f*mu*mu*mu*mu;
            float skew = m3 / (sd*sd*sd + 1e-8f);
            float kurt = m4 / (varu*varu + 1e-8f) - 3.f;
            int h = c0 + t*4 + k;
            f[h]        = mu;
            f[HH + h]   = sd;
            f[3*HH + h] = MX[k];
            f[4*HH + h] = MN[k];
            f[5*HH + h] = skew;
            f[6*HH + h] = kurt;
        }
    }
}

// ---------------- reduce row norms -> batch mean -> fill feature slot ----------------
__global__ void __launch_bounds__(1024) k_nrmfin() {
    int b = blockIdx.x, t = threadIdx.x;
    float s = 0.f;
    for (int i = t; i < SS; i += 1024) s += sqrtf(d_rowsq[b*SS + i]);
    __shared__ float red[1024];
    red[t] = s; __syncthreads();
    for (int o = 512; o; o >>= 1) { if (t < o) red[t] += red[t+o]; __syncthreads(); }
    float nv = red[0] * (1.f/(float)SS);
    for (int h = t; h < HH; h += 1024) d_feats[b*F7 + 2*HH + h] = nv;
}

// ---------------- generic FC: out[4][N] += in[4][K] @ W[K][N] (split-K atomics) ----------------
__global__ void __launch_bounds__(256) k_fc(const float* __restrict__ W,
                                            int sel, int K, int N, int KS) {
    extern __shared__ float insh[];            // [4][KS]
    const float* in  = (sel == 0) ? d_feats : (sel == 1 ? d_h1 : d_h2);
    float*       out = (sel == 0) ? d_a1    : (sel == 1 ? d_a2 : d_a3);
    int t  = threadIdx.x;
    int j  = blockIdx.x*256 + t;
    int k0 = blockIdx.y*KS;
    for (int e = t; e < 4*KS; e += 256) {
        int bb = e / KS, kk = e % KS;
        insh[e] = in[bb*K + k0 + kk];
    }
    __syncthreads();
    float a0=0.f, a1=0.f, a2=0.f, a3=0.f;
    const float* w = W + (size_t)k0*N + j;
    for (int k = 0; k < KS; k++) {
        float wv = w[(size_t)k*N];
        a0 += insh[k]*wv; a1 += insh[KS+k]*wv;
        a2 += insh[2*KS+k]*wv; a3 += insh[3*KS+k]*wv;
    }
    atomicAdd(&out[j],       a0);
    atomicAdd(&out[N+j],     a1);
    atomicAdd(&out[2*N+j],   a2);
    atomicAdd(&out[3*N+j],   a3);
}

// ---------------- bias + LayerNorm + ReLU ----------------
__global__ void __launch_bounds__(256) k_ln(int sel, const float* __restrict__ bias,
                                            const float* __restrict__ gam,
                                            const float* __restrict__ bet, int N) {
    const float* a   = (sel == 0) ? d_a1 : d_a2;
    float*       out = (sel == 0) ? d_h1 : d_h2;
    int b = blockIdx.x, t = threadIdx.x;
    int cnt = N >> 8;
    float v[4];
    float s = 0.f, s2 = 0.f;
    for (int q = 0; q < cnt; q++) {
        int i = q*256 + t;
        float x = a[b*N + i] + bias[i];
        v[q] = x; s += x; s2 += x*x;
    }
    __shared__ float red[256];
    red[t] = s; __syncthreads();
    for (int o = 128; o; o >>= 1) { if (t < o) red[t] += red[t+o]; __syncthreads(); }
    float mu = red[0] / (float)N;
    __syncthreads();
    red[t] = s2; __syncthreads();
    for (int o = 128; o; o >>= 1) { if (t < o) red[t] += red[t+o]; __syncthreads(); }
    float var = red[0] / (float)N - mu*mu;
    float rs = rsqrtf(var + 1e-5f);
    for (int q = 0; q < cnt; q++) {
        int i = q*256 + t;
        float y = (v[q] - mu)*rs*gam[i] + bet[i];
        out[b*N + i] = fmaxf(y, 0.f);
    }
}

// ---------------- U/V generation (float4 weight loads, writes transposed bf16) ----------------
__global__ void __launch_bounds__(256) k_uv(const float* __restrict__ Wu, const float* __restrict__ bu,
                                            const float* __restrict__ Wv, const float* __restrict__ bv,
                                            const float* __restrict__ b3,
                                            const float* __restrict__ su, const float* __restrict__ sv) {
    __shared__ float h3s[BB*256];
    int t = threadIdx.x;
    #pragma unroll
    for (int q = 0; q < 4; q++) {
        int idx = q*256 + t;
        h3s[idx] = fmaxf(d_a3[idx] + b3[t], 0.f);
    }
    __syncthreads();
    bool isV = blockIdx.x >= 128;
    int j0 = (blockIdx.x & 127)*1024 + t*4;    // 4 outputs per thread
    const float* W = isV ? Wv : Wu;
    float4 acc[BB];
    #pragma unroll
    for (int b = 0; b < BB; b++) { acc[b].x=0.f; acc[b].y=0.f; acc[b].z=0.f; acc[b].w=0.f; }
    const float4* w4 = (const float4*)(W + j0);
    for (int i = 0; i < 256; i++) {
        float4 wv = w4[(size_t)i * (HH*RR/4)];
        #pragma unroll
        for (int b = 0; b < BB; b++) {
            float h = h3s[b*256 + i];
            acc[b].x += h*wv.x; acc[b].y += h*wv.y;
            acc[b].z += h*wv.z; acc[b].w += h*wv.w;
        }
    }
    if (!isV) {
        float4 bb = *(const float4*)&bu[j0];
        float sc = *su;
        int h = j0 >> 6, r0 = j0 & 63;         // U reshape: j -> (h, r)
        #pragma unroll
        for (int b = 0; b < BB; b++) {
            float av[4] = {(acc[b].x+bb.x)*sc, (acc[b].y+bb.y)*sc,
                           (acc[b].z+bb.z)*sc, (acc[b].w+bb.w)*sc};
            #pragma unroll
            for (int k = 0; k < 4; k++)
                d_Ut[((size_t)b*RR + r0 + k)*HH + h] = __float2bfloat16(av[k]);
        }
    } else {
        float4 bb = *(const float4*)&bv[j0];
        float sc = *sv;
        int r = j0 >> 11, h0 = j0 & 2047;      // V reshape: j -> (r, h)
        #pragma unroll
        for (int b = 0; b < BB; b++) {
            float av[4] = {(acc[b].x+bb.x)*sc, (acc[b].y+bb.y)*sc,
                           (acc[b].z+bb.z)*sc, (acc[b].w+bb.w)*sc};
            #pragma unroll
            for (int k = 0; k < 4; k++)
                d_Vt[((size_t)b*HH + h0 + k)*RR + r] = __float2bfloat16(av[k]);
        }
    }
}

// ---------------- fused output: out = rw*X + (1-rw)*(X@U)@V via mma.sync bf16 ----------------
__device__ __forceinline__ uint32_t packf2(float lo, float hi) {
    __nv_bfloat162 h = __floats2bfloat162_rn(lo, hi);
    return *reinterpret_cast<uint32_t*>(&h);
}
__device__ __forceinline__ void mma_bf16(float& c0, float& c1, float& c2, float& c3,
                                         uint32_t a0, uint32_t a1, uint32_t a2, uint32_t a3,
                                         uint32_t b0, uint32_t b1) {
    asm volatile("mma.sync.aligned.m16n8k16.row.col.f32.bf16.bf16.f32 "
                 "{%0,%1,%2,%3}, {%4,%5,%6,%7}, {%8,%9}, {%0,%1,%2,%3};"
                 : "+f"(c0), "+f"(c1), "+f"(c2), "+f"(c3)
                 : "r"(a0), "r"(a1), "r"(a2), "r"(a3), "r"(b0), "r"(b1));
}
__device__ __forceinline__ void cpa16(uint32_t dst, const void* src) {
    asm volatile("{ .reg .u64 g; cvta.to.global.u64 g, %1; "
                 "cp.async.cg.shared.global [%0], [g], 16; }"
                 :: "r"(dst), "l"(src) : "memory");
}

__global__ void __launch_bounds__(128) k_fused(const float* __restrict__ X,
                                               float* __restrict__ out,
                                               const float* __restrict__ rw_p) {
    const float rw = *rw_p;
    const float cw = 1.f - rw;
    int b  = blockIdx.y;
    int m0 = blockIdx.x * 64;                  // 64-row M tile
    int t  = threadIdx.x, w = t >> 5, lane = t & 31;
    int g  = lane >> 2, t4 = lane & 3;
    __shared__ __nv_bfloat16 sB[2][64][72];    // double buffer, conflict-free stride (144B, 16B-aligned)
    const float* Xb = X   + (size_t)b*SS*HH;
    float*       Ob = out + (size_t)b*SS*HH;
    int row0 = m0 + w*16 + g;
    uint32_t sbase = (uint32_t)__cvta_generic_to_shared(&sB[0][0][0]);

    const __nv_bfloat16* Ut = d_Ut + (size_t)b*RR*HH;
    const __nv_bfloat16* Vt = d_Vt + (size_t)b*HH*RR;

    // async 64x64 bf16 tile load: 512 16-byte chunks, 4 per thread
    auto load_tile = [&](int buf, const __nv_bfloat16* src, int k0, int srcStride) {
        #pragma unroll
        for (int q = 0; q < 4; q++) {
            int e = t + q*128;
            int r = e >> 3, pos = e & 7;
            uint32_t dst = sbase + buf*9216u + (uint32_t)(r*144 + pos*16);
            cpa16(dst, src + (size_t)r*srcStride + k0 + pos*8);
        }
        asm volatile("cp.async.commit_group;" ::: "memory");
    };

    // register X fetch for one 64-col K slab (16 float2 per thread)
    auto loadX = [&](float2* dst, int k0) {
        #pragma unroll
        for (int ks = 0; ks < 4; ks++) {
            int kk = k0 + ks*16;
            dst[ks*4+0] = *(const float2*)&Xb[(size_t)row0*HH     + kk + 2*t4];
            dst[ks*4+1] = *(const float2*)&Xb[(size_t)(row0+8)*HH + kk + 2*t4];
            dst[ks*4+2] = *(const float2*)&Xb[(size_t)row0*HH     + kk + 8 + 2*t4];
            dst[ks*4+3] = *(const float2*)&Xb[(size_t)(row0+8)*HH + kk + 8 + 2*t4];
        }
    };

    // ---- phase 1: P[64x64] = X_tile @ U_b  (K = 2048) ----
    float p[8][4];
    #pragma unroll
    for (int nb = 0; nb < 8; nb++)
        { p[nb][0]=0.f; p[nb][1]=0.f; p[nb][2]=0.f; p[nb][3]=0.f; }

    float2 xr[16], xn[16];
    load_tile(0, Ut, 0, HH);
    loadX(xr, 0);
    for (int kc = 0; kc < 32; kc++) {
        int buf = kc & 1;
        if (kc + 1 < 32) {
            load_tile(buf^1, Ut, (kc+1)*64, HH);
            loadX(xn, (kc+1)*64);              // prefetch next X slab into regs
            asm volatile("cp.async.wait_group 1;" ::: "memory");
        } else {
            asm volatile("cp.async.wait_group 0;" ::: "memory");
        }
        __syncthreads();
        #pragma unroll
        for (int ks = 0; ks < 4; ks++) {
            uint32_t a0 = packf2(xr[ks*4+0].x, xr[ks*4+0].y);
            uint32_t a1 = packf2(xr[ks*4+1].x, xr[ks*4+1].y);
            uint32_t a2 = packf2(xr[ks*4+2].x, xr[ks*4+2].y);
            uint32_t a3 = packf2(xr[ks*4+3].x, xr[ks*4+3].y);
            #pragma unroll
            for (int nb = 0; nb < 8; nb++) {
                uint32_t b0 = *(const uint32_t*)&sB[buf][nb*8+g][ks*16 + 2*t4];
                uint32_t b1 = *(const uint32_t*)&sB[buf][nb*8+g][ks*16 + 8 + 2*t4];
                mma_bf16(p[nb][0], p[nb][1], p[nb][2], p[nb][3], a0, a1, a2, a3, b0, b1);
            }
        }
        #pragma unroll
        for (int i = 0; i < 16; i++) xr[i] = xn[i];
        __syncthreads();
    }

    // P accumulator fragments == A fragments of phase 2 (pack to bf16x2)
    uint32_t pA[4][4];
    #pragma unroll
    for (int kb = 0; kb < 4; kb++) {
        pA[kb][0] = packf2(p[2*kb][0],   p[2*kb][1]);
        pA[kb][1] = packf2(p[2*kb][2],   p[2*kb][3]);
        pA[kb][2] = packf2(p[2*kb+1][0], p[2*kb+1][1]);
        pA[kb][3] = packf2(p[2*kb+1][2], p[2*kb+1][3]);
    }

    // ---- phase 2: out_tile = rw*X + cw*(P @ V_b)  (K = 64, N = 2048) ----
    load_tile(0, Vt, 0, RR);
    for (int nc = 0; nc < 32; nc++) {
        int buf = nc & 1;
        if (nc + 1 < 32) {
            load_tile(buf^1, Vt + (size_t)(nc+1)*64*RR, 0, RR);
            asm volatile("cp.async.wait_group 1;" ::: "memory");
        } else {
            asm volatile("cp.async.wait_group 0;" ::: "memory");
        }
        __syncthreads();
        int h0 = nc*64;
        // hoist residual X loads above the mma chain (latency overlap)
        float2 rx0[8], rx1[8];
        #pragma unroll
        for (int nb = 0; nb < 8; nb++) {
            int col = h0 + nb*8 + 2*t4;
            rx0[nb] = *(const float2*)&Xb[(size_t)row0*HH + col];
            rx1[nb] = *(const float2*)&Xb[(size_t)(row0+8)*HH + col];
        }
        float o[8][4];
        #pragma unroll
        for (int nb = 0; nb < 8; nb++)
            { o[nb][0]=0.f; o[nb][1]=0.f; o[nb][2]=0.f; o[nb][3]=0.f; }
        #pragma unroll
        for (int kb = 0; kb < 4; kb++) {
            #pragma unroll
            for (int nb = 0; nb < 8; nb++) {
                uint32_t b0 = *(const uint32_t*)&sB[buf][nb*8+g][kb*16 + 2*t4];
                uint32_t b1 = *(const uint32_t*)&sB[buf][nb*8+g][kb*16 + 8 + 2*t4];
                mma_bf16(o[nb][0], o[nb][1], o[nb][2], o[nb][3],
                         pA[kb][0], pA[kb][1], pA[kb][2], pA[kb][3], b0, b1);
            }
        }
        __syncthreads();
        #pragma unroll
        for (int nb = 0; nb < 8; nb++) {
            int col = h0 + nb*8 + 2*t4;
            size_t i0 = (size_t)row0*HH + col;
            size_t i1 = (size_t)(row0+8)*HH + col;
            float2 r0 = { rw*rx0[nb].x + cw*o[nb][0], rw*rx0[nb].y + cw*o[nb][1] };
            float2 r1 = { rw*rx1[nb].x + cw*o[nb][2], rw*rx1[nb].y + cw*o[nb][3] };
            *(float2*)&Ob[i0] = r0;
            *(float2*)&Ob[i1] = r1;
        }
    }
}

// ---------------- launch ----------------
extern "C" void kernel_launch(void* const* d_in, const int* in_sizes, int n_in,
                              void* d_out, int out_size) {
    const float* X   = (const float*)d_in[0];
    const float* W1  = (const float*)d_in[1];
    const float* b1  = (const float*)d_in[2];
    const float* g1  = (const float*)d_in[3];
    const float* be1 = (const float*)d_in[4];
    const float* W2  = (const float*)d_in[5];
    const float* b2  = (const float*)d_in[6];
    const float* g2  = (const float*)d_in[7];
    const float* be2 = (const float*)d_in[8];
    const float* W3  = (const float*)d_in[9];
    const float* b3  = (const float*)d_in[10];
    const float* Wu  = (const float*)d_in[11];
    const float* bu  = (const float*)d_in[12];
    const float* Wv  = (const float*)d_in[13];
    const float* bv  = (const float*)d_in[14];
    const float* su  = (const float*)d_in[15];
    const float* sv  = (const float*)d_in[16];
    const float* rw  = (const float*)d_in[17];
    float* out = (float*)d_out;

    k_init<<<64, 256>>>();
    k_colstats<<<dim3(16, BB), 512>>>(X);
    k_nrmfin<<<BB, 1024>>>();
    k_fc<<<dim3(4, 32), 256, 4*448*sizeof(float)>>>(W1, 0, F7,  1024, 448);
    k_ln<<<BB, 256>>>(0, b1, g1, be1, 1024);
    k_fc<<<dim3(2, 8), 256, 4*128*sizeof(float)>>>(W2, 1, 1024, 512, 128);
    k_ln<<<BB, 256>>>(1, b2, g2, be2, 512);
    k_fc<<<dim3(1, 8), 256, 4*64*sizeof(float)>>>(W3, 2, 512, 256, 64);
    k_uv<<<256, 256>>>(Wu, bu, Wv, bv, b3, su, sv);
    k_fused<<<dim3(64, BB), 128>>>(X, out, rw);
}

// round 14
// speedup vs baseline: 1.6516x; 1.6516x over previous
#include <cuda_runtime.h>
#include <cuda_bf16.h>
#include <cstdint>
#include <math.h>

#define HH 2048
#define SS 4096
#define BB 4
#define RR 64
#define F7 (7*HH)

// ---------------- scratch (device globals; no allocation) ----------------
__device__ float d_rownrm[BB*SS];
__device__ float d_feats[BB*F7];
__device__ float d_a1[BB*1024];
__device__ float d_h1[BB*1024];
__device__ float d_a2[BB*512];
__device__ float d_h2[BB*512];
__device__ float d_a3[BB*256];
__device__ __nv_bfloat16 d_Ut[BB*RR*HH];   // [b][r][h]  (U transposed)
__device__ __nv_bfloat16 d_Vt[BB*HH*RR];   // [b][h][r]  (V transposed)

// ---------------- init (zero the atomic accumulators) ----------------
__global__ void k_init() {
    int i = blockIdx.x*256 + threadIdx.x;
    if (i < BB*1024) d_a1[i] = 0.f;
    if (i < BB*512)  d_a2[i] = 0.f;
    if (i < BB*256)  d_a3[i] = 0.f;
}

// ---------------- column stats: per-lane float4 accumulation, no shfl ----------------
__global__ void __launch_bounds__(512) k_colstats(const float* __restrict__ X) {
    int b  = blockIdx.y;
    int c0 = blockIdx.x * 128;                 // 128 cols per block (32 lanes x 4)
    int t  = threadIdx.x, w = t >> 5, lane = t & 31;
    const float4* base = (const float4*)(X + (size_t)b*SS*HH + c0);
    float s1[4] = {0,0,0,0}, s2[4] = {0,0,0,0}, s3[4] = {0,0,0,0}, s4[4] = {0,0,0,0};
    float mx[4] = {-INFINITY,-INFINITY,-INFINITY,-INFINITY};
    float mn[4] = { INFINITY, INFINITY, INFINITY, INFINITY};
    for (int r = w; r < SS; r += 16) {
        float4 v = base[(size_t)r*(HH/4) + lane];
        float xs[4] = {v.x, v.y, v.z, v.w};
        #pragma unroll
        for (int k = 0; k < 4; k++) {
            float x = xs[k], x2 = x*x;
            s1[k] += x; s2[k] += x2; s3[k] += x2*x; s4[k] += x2*x2;
            mx[k] = fmaxf(mx[k], x); mn[k] = fminf(mn[k], x);
        }
    }
    __shared__ float sm[6][16][32][4];         // 48 KB
    #pragma unroll
    for (int k = 0; k < 4; k++) {
        sm[0][w][lane][k] = s1[k]; sm[1][w][lane][k] = s2[k];
        sm[2][w][lane][k] = s3[k]; sm[3][w][lane][k] = s4[k];
        sm[4][w][lane][k] = mx[k]; sm[5][w][lane][k] = mn[k];
    }
    __syncthreads();
    if (t < 32) {
        float S1[4], S2[4], S3[4], S4[4], MX[4], MN[4];
        #pragma unroll
        for (int k = 0; k < 4; k++) {
            S1[k]=0.f; S2[k]=0.f; S3[k]=0.f; S4[k]=0.f;
            MX[k]=-INFINITY; MN[k]=INFINITY;
        }
        for (int g = 0; g < 16; g++) {
            #pragma unroll
            for (int k = 0; k < 4; k++) {
                S1[k] += sm[0][g][t][k]; S2[k] += sm[1][g][t][k];
                S3[k] += sm[2][g][t][k]; S4[k] += sm[3][g][t][k];
                MX[k] = fmaxf(MX[k], sm[4][g][t][k]);
                MN[k] = fminf(MN[k], sm[5][g][t][k]);
            }
        }
        const float inv = 1.f / (float)SS;
        float* f = d_feats + b*F7;
        #pragma unroll
        for (int k = 0; k < 4; k++) {
            float mu = S1[k]*inv, E2 = S2[k]*inv, E3 = S3[k]*inv, E4 = S4[k]*inv;
            float varu = fmaxf((S2[k] - (float)SS*mu*mu) / (float)(SS-1), 0.f);
            float sd = sqrtf(varu);
            float m3 = E3 - 3.f*mu*E2 + 2.f*mu*mu*mu;
            float m4 = E4 - 4.f*mu*E3 + 6.f*mu*mu*E2 - 3.f*mu*mu*mu*mu;
            float skew = m3 / (sd*sd*sd + 1e-8f);
            float kurt = m4 / (varu*varu + 1e-8f) - 3.f;
            int h = c0 + t*4 + k;
            f[h]        = mu;
            f[HH + h]   = sd;
            f[3*HH + h] = MX[k];
            f[4*HH + h] = MN[k];
            f[5*HH + h] = skew;
            f[6*HH + h] = kurt;
        }
    }
}

// ---------------- row norms: one warp per row, coalesced float4 ----------------
__global__ void __launch_bounds__(256) k_rownrm(const float* __restrict__ X) {
    int wid  = (blockIdx.x*256 + threadIdx.x) >> 5;   // 0..16383
    int lane = threadIdx.x & 31;
    const float4* row = (const float4*)(X + (size_t)wid*HH);
    float acc = 0.f;
    #pragma unroll
    for (int i = 0; i < 16; i++) {
        float4 v = row[lane + i*32];
        acc += v.x*v.x + v.y*v.y + v.z*v.z + v.w*v.w;
    }
    #pragma unroll
    for (int o = 16; o; o >>= 1) acc += __shfl_xor_sync(0xffffffffu, acc, o);
    if (lane == 0) d_rownrm[wid] = sqrtf(acc);
}

// ---------------- reduce row norms -> batch mean -> fill feature slot ----------------
__global__ void __launch_bounds__(1024) k_nrmfin() {
    int b = blockIdx.x, t = threadIdx.x;
    float s = 0.f;
    for (int i = t; i < SS; i += 1024) s += d_rownrm[b*SS + i];
    __shared__ float red[1024];
    red[t] = s; __syncthreads();
    for (int o = 512; o; o >>= 1) { if (t < o) red[t] += red[t+o]; __syncthreads(); }
    float nv = red[0] * (1.f/(float)SS);
    for (int h = t; h < HH; h += 1024) d_feats[b*F7 + 2*HH + h] = nv;
}

// ------- FC: out[4][N] += in[4][K] @ W[K][N], templated split-K, float4 loads -------
// block = N/4 threads (thread owns 4 consecutive output cols), grid.x = K/KS
// SEL resolves in/out pointers IN DEVICE CODE (host cannot take __device__ addrs)
template<int K, int N, int KS, int SEL>
__global__ void __launch_bounds__(256) k_fc_t(const float* __restrict__ W) {
    const float* in  = (SEL == 0) ? d_feats : (SEL == 1 ? d_h1 : d_h2);
    float*       out = (SEL == 0) ? d_a1    : (SEL == 1 ? d_a2 : d_a3);
    __shared__ float insh[BB*KS];
    int t  = threadIdx.x;
    int k0 = blockIdx.x*KS;
    for (int e = t; e < BB*KS; e += blockDim.x) {
        int bb = e / KS, kk = e % KS;
        insh[e] = in[bb*K + k0 + kk];
    }
    __syncthreads();
    float4 acc[BB];
    #pragma unroll
    for (int b = 0; b < BB; b++) { acc[b].x=0.f; acc[b].y=0.f; acc[b].z=0.f; acc[b].w=0.f; }
    const float4* w4 = (const float4*)W + (size_t)k0*(N/4) + t;
    #pragma unroll 16
    for (int k = 0; k < KS; k++) {
        float4 wv = w4[(size_t)k*(N/4)];
        #pragma unroll
        for (int b = 0; b < BB; b++) {
            float h = insh[b*KS + k];
            acc[b].x += h*wv.x; acc[b].y += h*wv.y;
            acc[b].z += h*wv.z; acc[b].w += h*wv.w;
        }
    }
    int j = t*4;
    #pragma unroll
    for (int b = 0; b < BB; b++) {
        atomicAdd(&out[b*N + j    ], acc[b].x);
        atomicAdd(&out[b*N + j + 1], acc[b].y);
        atomicAdd(&out[b*N + j + 2], acc[b].z);
        atomicAdd(&out[b*N + j + 3], acc[b].w);
    }
}

// ---------------- bias + LayerNorm + ReLU ----------------
__global__ void __launch_bounds__(256) k_ln(int sel, const float* __restrict__ bias,
                                            const float* __restrict__ gam,
                                            const float* __restrict__ bet, int N) {
    const float* a   = (sel == 0) ? d_a1 : d_a2;
    float*       out = (sel == 0) ? d_h1 : d_h2;
    int b = blockIdx.x, t = threadIdx.x;
    int cnt = N >> 8;
    float v[4];
    float s = 0.f, s2 = 0.f;
    for (int q = 0; q < cnt; q++) {
        int i = q*256 + t;
        float x = a[b*N + i] + bias[i];
        v[q] = x; s += x; s2 += x*x;
    }
    __shared__ float red[256];
    red[t] = s; __syncthreads();
    for (int o = 128; o; o >>= 1) { if (t < o) red[t] += red[t+o]; __syncthreads(); }
    float mu = red[0] / (float)N;
    __syncthreads();
    red[t] = s2; __syncthreads();
    for (int o = 128; o; o >>= 1) { if (t < o) red[t] += red[t+o]; __syncthreads(); }
    float var = red[0] / (float)N - mu*mu;
    float rs = rsqrtf(var + 1e-5f);
    for (int q = 0; q < cnt; q++) {
        int i = q*256 + t;
        float y = (v[q] - mu)*rs*gam[i] + bet[i];
        out[b*N + i] = fmaxf(y, 0.f);
    }
}

// ---------------- U/V generation (float4 weight loads, writes transposed bf16) ----------------
__global__ void __launch_bounds__(256) k_uv(const float* __restrict__ Wu, const float* __restrict__ bu,
                                            const float* __restrict__ Wv, const float* __restrict__ bv,
                                            const float* __restrict__ b3,
                                            const float* __restrict__ su, const float* __restrict__ sv) {
    __shared__ float h3s[BB*256];
    int t = threadIdx.x;
    #pragma unroll
    for (int q = 0; q < 4; q++) {
        int idx = q*256 + t;
        h3s[idx] = fmaxf(d_a3[idx] + b3[t], 0.f);
    }
    __syncthreads();
    bool isV = blockIdx.x >= 128;
    int j0 = (blockIdx.x & 127)*1024 + t*4;    // 4 outputs per thread
    const float* W = isV ? Wv : Wu;
    float4 acc[BB];
    #pragma unroll
    for (int b = 0; b < BB; b++) { acc[b].x=0.f; acc[b].y=0.f; acc[b].z=0.f; acc[b].w=0.f; }
    const float4* w4 = (const float4*)(W + j0);
    #pragma unroll 8
    for (int i = 0; i < 256; i++) {
        float4 wv = w4[(size_t)i * (HH*RR/4)];
        #pragma unroll
        for (int b = 0; b < BB; b++) {
            float h = h3s[b*256 + i];
            acc[b].x += h*wv.x; acc[b].y += h*wv.y;
            acc[b].z += h*wv.z; acc[b].w += h*wv.w;
        }
    }
    if (!isV) {
        float4 bb = *(const float4*)&bu[j0];
        float sc = *su;
        int h = j0 >> 6, r0 = j0 & 63;         // U reshape: j -> (h, r)
        #pragma unroll
        for (int b = 0; b < BB; b++) {
            float av[4] = {(acc[b].x+bb.x)*sc, (acc[b].y+bb.y)*sc,
                           (acc[b].z+bb.z)*sc, (acc[b].w+bb.w)*sc};
            #pragma unroll
            for (int k = 0; k < 4; k++)
                d_Ut[((size_t)b*RR + r0 + k)*HH + h] = __float2bfloat16(av[k]);
        }
    } else {
        float4 bb = *(const float4*)&bv[j0];
        float sc = *sv;
        int r = j0 >> 11, h0 = j0 & 2047;      // V reshape: j -> (r, h)
        #pragma unroll
        for (int b = 0; b < BB; b++) {
            float av[4] = {(acc[b].x+bb.x)*sc, (acc[b].y+bb.y)*sc,
                           (acc[b].z+bb.z)*sc, (acc[b].w+bb.w)*sc};
            #pragma unroll
            for (int k = 0; k < 4; k++)
                d_Vt[((size_t)b*HH + h0 + k)*RR + r] = __float2bfloat16(av[k]);
        }
    }
}

// ---------------- fused output: out = rw*X + (1-rw)*(X@U)@V via mma.sync bf16 ----------------
__device__ __forceinline__ uint32_t packf2(float lo, float hi) {
    __nv_bfloat162 h = __floats2bfloat162_rn(lo, hi);
    return *reinterpret_cast<uint32_t*>(&h);
}
__device__ __forceinline__ void mma_bf16(float& c0, float& c1, float& c2, float& c3,
                                         uint32_t a0, uint32_t a1, uint32_t a2, uint32_t a3,
                                         uint32_t b0, uint32_t b1) {
    asm volatile("mma.sync.aligned.m16n8k16.row.col.f32.bf16.bf16.f32 "
                 "{%0,%1,%2,%3}, {%4,%5,%6,%7}, {%8,%9}, {%0,%1,%2,%3};"
                 : "+f"(c0), "+f"(c1), "+f"(c2), "+f"(c3)
                 : "r"(a0), "r"(a1), "r"(a2), "r"(a3), "r"(b0), "r"(b1));
}
__device__ __forceinline__ void cpa16(uint32_t dst, const void* src) {
    asm volatile("{ .reg .u64 g; cvta.to.global.u64 g, %1; "
                 "cp.async.cg.shared.global [%0], [g], 16; }"
                 :: "r"(dst), "l"(src) : "memory");
}

__global__ void __launch_bounds__(128) k_fused(const float* __restrict__ X,
                                               float* __restrict__ out,
                                               const float* __restrict__ rw_p) {
    const float rw = *rw_p;
    const float cw = 1.f - rw;
    int b  = blockIdx.y;
    int m0 = blockIdx.x * 64;                  // 64-row M tile
    int t  = threadIdx.x, w = t >> 5, lane = t & 31;
    int g  = lane >> 2, t4 = lane & 3;
    __shared__ __nv_bfloat16 sB[2][64][72];    // double buffer, conflict-free stride (144B)
    const float* Xb = X   + (size_t)b*SS*HH;
    float*       Ob = out + (size_t)b*SS*HH;
    int row0 = m0 + w*16 + g;
    uint32_t sbase = (uint32_t)__cvta_generic_to_shared(&sB[0][0][0]);

    const __nv_bfloat16* Ut = d_Ut + (size_t)b*RR*HH;
    const __nv_bfloat16* Vt = d_Vt + (size_t)b*HH*RR;

    // async 64x64 bf16 tile load: 512 16-byte chunks, 4 per thread
    auto load_tile = [&](int buf, const __nv_bfloat16* src, int k0, int srcStride) {
        #pragma unroll
        for (int q = 0; q < 4; q++) {
            int e = t + q*128;
            int r = e >> 3, pos = e & 7;
            uint32_t dst = sbase + buf*9216u + (uint32_t)(r*144 + pos*16);
            cpa16(dst, src + (size_t)r*srcStride + k0 + pos*8);
        }
        asm volatile("cp.async.commit_group;" ::: "memory");
    };

    // register X fetch for one 64-col K slab (16 float2 per thread)
    auto loadX = [&](float2* dst, int k0) {
        #pragma unroll
        for (int ks = 0; ks < 4; ks++) {
            int kk = k0 + ks*16;
            dst[ks*4+0] = *(const float2*)&Xb[(size_t)row0*HH     + kk + 2*t4];
            dst[ks*4+1] = *(const float2*)&Xb[(size_t)(row0+8)*HH + kk + 2*t4];
            dst[ks*4+2] = *(const float2*)&Xb[(size_t)row0*HH     + kk + 8 + 2*t4];
            dst[ks*4+3] = *(const float2*)&Xb[(size_t)(row0+8)*HH + kk + 8 + 2*t4];
        }
    };

    // ---- phase 1: P[64x64] = X_tile @ U_b  (K = 2048) ----
    float p[8][4];
    #pragma unroll
    for (int nb = 0; nb < 8; nb++)
        { p[nb][0]=0.f; p[nb][1]=0.f; p[nb][2]=0.f; p[nb][3]=0.f; }

    float2 xr[16], xn[16];
    load_tile(0, Ut, 0, HH);
    loadX(xr, 0);
    for (int kc = 0; kc < 32; kc++) {
        int buf = kc & 1;
        if (kc + 1 < 32) {
            load_tile(buf^1, Ut, (kc+1)*64, HH);
            loadX(xn, (kc+1)*64);              // prefetch next X slab into regs
            asm volatile("cp.async.wait_group 1;" ::: "memory");
        } else {
            asm volatile("cp.async.wait_group 0;" ::: "memory");
        }
        __syncthreads();
        #pragma unroll
        for (int ks = 0; ks < 4; ks++) {
            uint32_t a0 = packf2(xr[ks*4+0].x, xr[ks*4+0].y);
            uint32_t a1 = packf2(xr[ks*4+1].x, xr[ks*4+1].y);
            uint32_t a2 = packf2(xr[ks*4+2].x, xr[ks*4+2].y);
            uint32_t a3 = packf2(xr[ks*4+3].x, xr[ks*4+3].y);
            #pragma unroll
            for (int nb = 0; nb < 8; nb++) {
                uint32_t b0 = *(const uint32_t*)&sB[buf][nb*8+g][ks*16 + 2*t4];
                uint32_t b1 = *(const uint32_t*)&sB[buf][nb*8+g][ks*16 + 8 + 2*t4];
                mma_bf16(p[nb][0], p[nb][1], p[nb][2], p[nb][3], a0, a1, a2, a3, b0, b1);
            }
        }
        #pragma unroll
        for (int i = 0; i < 16; i++) xr[i] = xn[i];
        __syncthreads();
    }

    // P accumulator fragments == A fragments of phase 2 (pack to bf16x2)
    uint32_t pA[4][4];
    #pragma unroll
    for (int kb = 0; kb < 4; kb++) {
        pA[kb][0] = packf2(p[2*kb][0],   p[2*kb][1]);
        pA[kb][1] = packf2(p[2*kb][2],   p[2*kb][3]);
        pA[kb][2] = packf2(p[2*kb+1][0], p[2*kb+1][1]);
        pA[kb][3] = packf2(p[2*kb+1][2], p[2*kb+1][3]);
    }

    // ---- phase 2: out_tile = rw*X + cw*(P @ V_b)  (K = 64, N = 2048) ----
    load_tile(0, Vt, 0, RR);
    for (int nc = 0; nc < 32; nc++) {
        int buf = nc & 1;
        if (nc + 1 < 32) {
            load_tile(buf^1, Vt + (size_t)(nc+1)*64*RR, 0, RR);
            asm volatile("cp.async.wait_group 1;" ::: "memory");
        } else {
            asm volatile("cp.async.wait_group 0;" ::: "memory");
        }
        __syncthreads();
        int h0 = nc*64;
        // hoist residual X loads above the mma chain (latency overlap)
        float2 rx0[8], rx1[8];
        #pragma unroll
        for (int nb = 0; nb < 8; nb++) {
            int col = h0 + nb*8 + 2*t4;
            rx0[nb] = *(const float2*)&Xb[(size_t)row0*HH + col];
            rx1[nb] = *(const float2*)&Xb[(size_t)(row0+8)*HH + col];
        }
        float o[8][4];
        #pragma unroll
        for (int nb = 0; nb < 8; nb++)
            { o[nb][0]=0.f; o[nb][1]=0.f; o[nb][2]=0.f; o[nb][3]=0.f; }
        #pragma unroll
        for (int kb = 0; kb < 4; kb++) {
            #pragma unroll
            for (int nb = 0; nb < 8; nb++) {
                uint32_t b0 = *(const uint32_t*)&sB[buf][nb*8+g][kb*16 + 2*t4];
                uint32_t b1 = *(const uint32_t*)&sB[buf][nb*8+g][kb*16 + 8 + 2*t4];
                mma_bf16(o[nb][0], o[nb][1], o[nb][2], o[nb][3],
                         pA[kb][0], pA[kb][1], pA[kb][2], pA[kb][3], b0, b1);
            }
        }
        __syncthreads();
        #pragma unroll
        for (int nb = 0; nb < 8; nb++) {
            int col = h0 + nb*8 + 2*t4;
            size_t i0 = (size_t)row0*HH + col;
            size_t i1 = (size_t)(row0+8)*HH + col;
            float2 r0 = { rw*rx0[nb].x + cw*o[nb][0], rw*rx0[nb].y + cw*o[nb][1] };
            float2 r1 = { rw*rx1[nb].x + cw*o[nb][2], rw*rx1[nb].y + cw*o[nb][3] };
            *(float2*)&Ob[i0] = r0;
            *(float2*)&Ob[i1] = r1;
        }
    }
}

// ---------------- launch ----------------
extern "C" void kernel_launch(void* const* d_in, const int* in_sizes, int n_in,
                              void* d_out, int out_size) {
    const float* X   = (const float*)d_in[0];
    const float* W1  = (const float*)d_in[1];
    const float* b1  = (const float*)d_in[2];
    const float* g1  = (const float*)d_in[3];
    const float* be1 = (const float*)d_in[4];
    const float* W2  = (const float*)d_in[5];
    const float* b2  = (const float*)d_in[6];
    const float* g2  = (const float*)d_in[7];
    const float* be2 = (const float*)d_in[8];
    const float* W3  = (const float*)d_in[9];
    const float* b3  = (const float*)d_in[10];
    const float* Wu  = (const float*)d_in[11];
    const float* bu  = (const float*)d_in[12];
    const float* Wv  = (const float*)d_in[13];
    const float* bv  = (const float*)d_in[14];
    const float* su  = (const float*)d_in[15];
    const float* sv  = (const float*)d_in[16];
    const float* rw  = (const float*)d_in[17];
    float* out = (float*)d_out;

    k_init<<<16, 256>>>();
    k_colstats<<<dim3(16, BB), 512>>>(X);
    k_rownrm<<<2048, 256>>>(X);
    k_nrmfin<<<BB, 1024>>>();
    k_fc_t<F7,   1024, 128, 0><<<112, 256>>>(W1);
    k_ln<<<BB, 256>>>(0, b1, g1, be1, 1024);
    k_fc_t<1024, 512,  64, 1><<<16, 128>>>(W2);
    k_ln<<<BB, 256>>>(1, b2, g2, be2, 512);
    k_fc_t<512,  256,  64, 2><<<8, 64>>>(W3);
    k_uv<<<256, 256>>>(Wu, bu, Wv, bv, b3, su, sv);
    k_fused<<<dim3(64, BB), 128>>>(X, out, rw);
}